// round 8
// baseline (speedup 1.0000x reference)
#include <cuda_runtime.h>
#include <cuda_bf16.h>
#include <cstdint>

#define B_    128
#define T_    1024
#define RNN_  1024
#define EMB_  512
#define ATT_  128
#define NF_   32
#define KS_   31
#define PAD_  15

// energies GEMM per 128-t tile: D[128,128] = A[t,192] * B[192,a], B dedup to 128 rows
// s0-3: Ahi x Bhi, s4-7: Alo x Bhi, s8-11: Ahi x Blo
#define LDAB_  136                              // bf16 elems per smem row (272 B)
#define OFF_B_    (128 * LDAB_ * 2)             // 34816
#define OFF_AWR_  (OFF_B_ + 128 * LDAB_ * 2)    // 69632: aw rows 2 x 1056 f
#define OFF_V_    (OFF_AWR_ + 8448)             // 78080
#define OFF_E_    (OFF_V_ + 512)                // 78592: energies 2 x 1024 f
#define OFF_RED_  (OFF_E_ + 8192)               // 86784
#define ESMEM_    (OFF_RED_ + 256)              // 87040

// ---------------- scratch (no allocations allowed) ----------------
__device__ float g_pq[B_ * ATT_];
__device__ __nv_bfloat16 g_W2bf[128 * 128];   // rows 0..63 hi, 64..127 lo (j>=62 zero)

// ---------------- helpers ----------------
__device__ __forceinline__ float tanh_fast(float x) {
    float y; asm("tanh.approx.f32 %0, %1;" : "=f"(y) : "f"(x)); return y;
}
__device__ __forceinline__ uint32_t smem_u32(const void* p) {
    uint32_t a;
    asm("{ .reg .u64 t; cvta.to.shared.u64 t, %1; cvt.u32.u64 %0, t; }" : "=r"(a) : "l"(p));
    return a;
}
__device__ __forceinline__ void ldsm_x4(uint32_t* r, uint32_t addr) {
    asm volatile("ldmatrix.sync.aligned.m8n8.x4.shared.b16 {%0,%1,%2,%3}, [%4];"
                 : "=r"(r[0]), "=r"(r[1]), "=r"(r[2]), "=r"(r[3]) : "r"(addr));
}
__device__ __forceinline__ void ldsm_x2t(uint32_t& b0, uint32_t& b1, uint32_t addr) {
    asm volatile("ldmatrix.sync.aligned.m8n8.x2.trans.shared.b16 {%0,%1}, [%2];"
                 : "=r"(b0), "=r"(b1) : "r"(addr));
}
__device__ __forceinline__ void mma_bf16(float* d, const uint32_t* a, uint32_t b0, uint32_t b1) {
    asm volatile("mma.sync.aligned.m16n8k16.row.col.f32.bf16.bf16.f32 "
                 "{%0,%1,%2,%3}, {%4,%5,%6,%7}, {%8,%9}, {%0,%1,%2,%3};"
                 : "+f"(d[0]), "+f"(d[1]), "+f"(d[2]), "+f"(d[3])
                 : "r"(a[0]), "r"(a[1]), "r"(a[2]), "r"(a[3]), "r"(b0), "r"(b1));
}

// ================= K1: prep =================
// blocks 0..255: pq, block = (b, a-half). 256 threads = 64 a x 4 k-quarters.
// block 256: W2 build.
__global__ __launch_bounds__(256) void prep_kernel(
    const float* __restrict__ hidden, const float* __restrict__ wq,
    const float* __restrict__ wconv,  const float* __restrict__ wloc)
{
    __shared__ float s_buf[8192];
    const int tid = threadIdx.x;

    if (blockIdx.x < 256) {
        const int b  = blockIdx.x >> 1;
        const int a0 = (blockIdx.x & 1) * 64;
        float* s_h    = s_buf;            // 1024 floats
        float* s_part = s_buf + 1024;     // [4][64]

        // stage hidden row
        #pragma unroll
        for (int i = 0; i < 4; ++i)
            s_h[tid + 256 * i] = hidden[(size_t)b * RNN_ + tid + 256 * i];
        __syncthreads();

        const int a  = tid & 63;
        const int kq = tid >> 6;          // 0..3
        const float* wqp = wq + (size_t)(kq * 256) * ATT_ + a0 + a;
        const float* hp  = s_h + kq * 256;

        float c0 = 0.f, c1 = 0.f, c2 = 0.f, c3 = 0.f;
        #pragma unroll 16
        for (int k = 0; k < 256; k += 4) {
            c0 = fmaf(hp[k + 0], __ldg(wqp + (size_t)(k + 0) * ATT_), c0);
            c1 = fmaf(hp[k + 1], __ldg(wqp + (size_t)(k + 1) * ATT_), c1);
            c2 = fmaf(hp[k + 2], __ldg(wqp + (size_t)(k + 2) * ATT_), c2);
            c3 = fmaf(hp[k + 3], __ldg(wqp + (size_t)(k + 3) * ATT_), c3);
        }
        s_part[kq * 64 + a] = (c0 + c1) + (c2 + c3);
        __syncthreads();
        if (tid < 64) {
            float r = (s_part[tid] + s_part[64 + tid])
                    + (s_part[128 + tid] + s_part[192 + tid]);
            g_pq[b * ATT_ + a0 + tid] = r;
        }
    } else {
        // W2[j,a] = sum_f wconv[f*62+j] * wloc[f*128+a], j in [0,62)
        float* s_W2 = s_buf;
        for (int m = tid; m < 62 * 128; m += 256) {
            int j = m >> 7, a = m & 127;
            float acc = 0.f;
            #pragma unroll 8
            for (int f = 0; f < NF_; ++f)
                acc = fmaf(wconv[f * 62 + j], wloc[f * ATT_ + a], acc);
            s_W2[m] = acc;
        }
        __syncthreads();
        for (int m = tid; m < 128 * 128; m += 256) {
            int row = m >> 7, a = m & 127;
            int seg = row >> 6, j = row & 63;
            __nv_bfloat16 out = __float2bfloat16_rn(0.f);
            if (j < 62) {
                float w = s_W2[j * 128 + a];
                __nv_bfloat16 hi = __float2bfloat16_rn(w);
                out = (seg == 0) ? hi : __float2bfloat16_rn(w - __bfloat162float(hi));
            }
            g_W2bf[m] = out;
        }
    }
}

// ============ K2: energies (MMA over 8 t-tiles, 16 warps) + fused softmax, 1 block/b ============
__global__ __launch_bounds__(512, 1) void energies_softmax_kernel(
    const float* __restrict__ aw,      // [B,2,T]
    const float* __restrict__ pmem,    // [B,T,ATT]
    const float* __restrict__ vvec,    // [ATT]
    const unsigned char* __restrict__ mask,
    float* __restrict__ out_w)
{
    extern __shared__ __align__(16) char sm[];
    const uint32_t sbase = smem_u32(sm);

    const int b    = blockIdx.x;
    const int tid  = threadIdx.x;
    const int wm   = tid >> 5, lane = tid & 31;
    const int slab = wm >> 1;          // 0..7: t rows [16*slab, 16*slab+16)
    const int nh   = wm & 1;           // 0..1: n-tiles [8*nh, 8*nh+8)

    float* s_awr = (float*)(sm + OFF_AWR_);   // [2][1056], s_awr[ch][i] = aw[gt=i-16]
    float* s_v   = (float*)(sm + OFF_V_);
    float* s_e   = (float*)(sm + OFF_E_);     // [2][1024] per-nh partials
    float* s_red = (float*)(sm + OFF_RED_);

    // ---- one-time staging ----
    {
        const uint32_t* gw = (const uint32_t*)g_W2bf;   // [128][64] u32
        for (int m = tid; m < 128 * 64; m += 512) {
            int r = m >> 6, c = m & 63;
            *(uint32_t*)(sm + OFF_B_ + r * (LDAB_ * 2) + c * 4) = gw[m];
        }
    }
    for (int idx = tid; idx < 2112; idx += 512) {
        int ch = idx / 1056, i = idx - ch * 1056;
        int gt = i - 16;
        s_awr[idx] = (gt >= 0 && gt < T_) ? aw[((size_t)b * 2 + ch) * T_ + gt] : 0.f;
    }
    if (tid < 128) {
        s_v[tid] = vvec[tid];
        float q = g_pq[b * ATT_ + tid];
        __nv_bfloat16 hi = __float2bfloat16_rn(q);
        __nv_bfloat16 lo = __float2bfloat16_rn(q - __bfloat162float(hi));
        __nv_bfloat16* sB = (__nv_bfloat16*)(sm + OFF_B_);
        sB[ 62 * LDAB_ + tid] = hi;
        sB[126 * LDAB_ + tid] = lo;
        __nv_bfloat16* arow = (__nv_bfloat16*)(sm + tid * (LDAB_ * 2));
        arow[62]  = __float2bfloat16_rn(1.f);
        arow[63]  = __float2bfloat16_rn(0.f);
        arow[126] = __float2bfloat16_rn(0.f);
        arow[127] = __float2bfloat16_rn(0.f);
    }

    const uint32_t aRowAddr = sbase + (16 * slab + (lane & 15)) * (LDAB_ * 2) + (lane >> 4) * 16;
    const uint32_t bRowAddr = sbase + OFF_B_ + (lane & 15) * (LDAB_ * 2) + nh * 128;
    const int rowL = tid >> 2;            // A row this thread builds
    const int jq   = tid & 3;             // 16-col group within the row

    // ---- 8 t-tiles ----
    for (int it = 0; it < 8; ++it) {
        const int t0g = it * 128;

        __syncthreads();
        {
            __nv_bfloat16* arow = (__nv_bfloat16*)(sm + rowL * (LDAB_ * 2));
            const int base0 = 1 + t0g + rowL;
            #pragma unroll
            for (int q = 0; q < 16; ++q) {
                int j = jq * 16 + q;
                if (j < 62) {
                    float x = (j < 31) ? s_awr[base0 + j] : s_awr[1056 + base0 + (j - 31)];
                    __nv_bfloat16 hi = __float2bfloat16_rn(x);
                    arow[j]      = hi;
                    arow[64 + j] = __float2bfloat16_rn(x - __bfloat162float(hi));
                }
            }
        }
        __syncthreads();

        float acc[8][4];
        #pragma unroll
        for (int n = 0; n < 8; ++n) {
            acc[n][0] = 0.f; acc[n][1] = 0.f; acc[n][2] = 0.f; acc[n][3] = 0.f;
        }
        #pragma unroll
        for (int s = 0; s < 12; ++s) {
            const int ksa = (s < 8) ? s : (s - 8);
            const int ksb = (s < 4) ? s : (s - 4);
            uint32_t af[4];
            ldsm_x4(af, aRowAddr + ksa * 32);
            const uint32_t bS = bRowAddr + ksb * 16 * (LDAB_ * 2);
            #pragma unroll
            for (int n = 0; n < 8; ++n) {
                uint32_t b0, b1;
                ldsm_x2t(b0, b1, bS + n * 16);
                mma_bf16(acc[n], af, b0, b1);
            }
        }

        {
            const int r  = lane >> 2;
            const int cq = (lane & 3) * 2;
            const int tA = t0g + 16 * slab + r;
            const float* pmA = pmem + ((size_t)b * T_ + tA) * ATT_;
            const float* pmB = pmA + 8 * ATT_;
            float eA = 0.f, eB = 0.f;
            #pragma unroll
            for (int n = 0; n < 8; ++n) {
                const int col = 64 * nh + 8 * n + cq;
                float2 v2 = *(const float2*)(s_v + col);
                float2 pa = *(const float2*)(pmA + col);
                float2 pb = *(const float2*)(pmB + col);
                eA = fmaf(tanh_fast(acc[n][0] + pa.x), v2.x, eA);
                eA = fmaf(tanh_fast(acc[n][1] + pa.y), v2.y, eA);
                eB = fmaf(tanh_fast(acc[n][2] + pb.x), v2.x, eB);
                eB = fmaf(tanh_fast(acc[n][3] + pb.y), v2.y, eB);
            }
            eA += __shfl_xor_sync(0xffffffffu, eA, 1);
            eA += __shfl_xor_sync(0xffffffffu, eA, 2);
            eB += __shfl_xor_sync(0xffffffffu, eB, 1);
            eB += __shfl_xor_sync(0xffffffffu, eB, 2);
            if ((lane & 3) == 0) {
                s_e[nh * 1024 + tA]     = eA;
                s_e[nh * 1024 + tA + 8] = eB;
            }
        }
    }
    __syncthreads();

    // ---- fused softmax over 1024 energies ----
    {
        float2 e0 = ((const float2*)s_e)[tid];
        float2 e1 = ((const float2*)(s_e + 1024))[tid];
        float2 ev; ev.x = e0.x + e1.x; ev.y = e0.y + e1.y;
        const uchar2 mk = ((const uchar2*)(mask + (size_t)b * T_))[tid];
        const float NINF = -__int_as_float(0x7f800000);
        if (mk.x) ev.x = NINF;
        if (mk.y) ev.y = NINF;

        float m = fmaxf(ev.x, ev.y);
        #pragma unroll
        for (int o = 16; o; o >>= 1) m = fmaxf(m, __shfl_xor_sync(0xffffffffu, m, o));
        if (lane == 0) s_red[wm] = m;
        __syncthreads();
        if (wm == 0) {
            float mm = (lane < 16) ? s_red[lane] : NINF;
            #pragma unroll
            for (int o = 8; o; o >>= 1) mm = fmaxf(mm, __shfl_xor_sync(0xffffffffu, mm, o));
            if (lane == 0) s_red[16] = mm;
        }
        __syncthreads();
        m = s_red[16];

        float2 p;
        p.x = expf(ev.x - m); p.y = expf(ev.y - m);
        float s = p.x + p.y;
        #pragma unroll
        for (int o = 16; o; o >>= 1) s += __shfl_xor_sync(0xffffffffu, s, o);
        if (lane == 0) s_red[32 + wm] = s;
        __syncthreads();
        if (wm == 0) {
            float ss = (lane < 16) ? s_red[32 + lane] : 0.f;
            #pragma unroll
            for (int o = 8; o; o >>= 1) ss += __shfl_xor_sync(0xffffffffu, ss, o);
            if (lane == 0) s_red[48] = ss;
        }
        __syncthreads();
        const float inv = 1.f / s_red[48];

        p.x *= inv; p.y *= inv;
        ((float2*)(out_w + (size_t)b * T_))[tid] = p;
    }
}

// ============ K3: context, single pass: grid (4, B_), 256 thr ============
__global__ __launch_bounds__(256) void context_kernel(
    const float* __restrict__ memory,   // [B,T,EMB]
    const float* __restrict__ out_w,    // weights [B,T]
    float* __restrict__ out)            // context [B,EMB]
{
    const int ec = blockIdx.x, b = blockIdx.y;
    const int tid = threadIdx.x;
    const int g = tid >> 5, l = tid & 31;

    __shared__ float s_w[T_];
    __shared__ float4 s_acc[256];

    #pragma unroll
    for (int i = 0; i < 4; ++i)
        s_w[tid + 256 * i] = out_w[(size_t)b * T_ + tid + 256 * i];
    __syncthreads();

    const float4* mem4 = (const float4*)memory + ((size_t)b * T_) * (EMB_ / 4) + ec * 32 + l;
    float4 acc = make_float4(0.f, 0.f, 0.f, 0.f);
    #pragma unroll 4
    for (int t = g; t < T_; t += 8) {
        float wt = s_w[t];
        float4 mv = __ldcs(mem4 + (size_t)t * (EMB_ / 4));
        acc.x = fmaf(wt, mv.x, acc.x);
        acc.y = fmaf(wt, mv.y, acc.y);
        acc.z = fmaf(wt, mv.z, acc.z);
        acc.w = fmaf(wt, mv.w, acc.w);
    }
    s_acc[tid] = acc;
    __syncthreads();
    if (g < 4) {
        float4 o = s_acc[tid + 128];
        acc.x += o.x; acc.y += o.y; acc.z += o.z; acc.w += o.w;
        s_acc[tid] = acc;
    }
    __syncthreads();
    if (g < 2) {
        float4 o = s_acc[tid + 64];
        acc.x += o.x; acc.y += o.y; acc.z += o.z; acc.w += o.w;
        s_acc[tid] = acc;
    }
    __syncthreads();
    if (g == 0) {
        float4 o = s_acc[tid + 32];
        acc.x += o.x; acc.y += o.y; acc.z += o.z; acc.w += o.w;
        ((float4*)out)[(size_t)b * (EMB_ / 4) + ec * 32 + l] = acc;
    }
}

// ============================ launch ============================
extern "C" void kernel_launch(void* const* d_in, const int* in_sizes, int n_in,
                              void* d_out, int out_size) {
    const float* hidden = (const float*)d_in[0];
    const float* memory = (const float*)d_in[1];
    const float* pmem   = (const float*)d_in[2];
    const float* awcat  = (const float*)d_in[3];
    const unsigned char* mask = (const unsigned char*)d_in[4];
    const float* wq     = (const float*)d_in[5];
    const float* wconv  = (const float*)d_in[6];
    const float* wloc   = (const float*)d_in[7];
    const float* vvec   = (const float*)d_in[8];

    float* out   = (float*)d_out;
    float* out_w = out + (size_t)B_ * EMB_;

    cudaFuncSetAttribute(energies_softmax_kernel,
                         cudaFuncAttributeMaxDynamicSharedMemorySize, ESMEM_);

    prep_kernel<<<257, 256>>>(hidden, wq, wconv, wloc);
    energies_softmax_kernel<<<B_, 512, ESMEM_>>>(awcat, pmem, vvec, mask, out_w);
    context_kernel<<<dim3(4, B_), 256>>>(memory, out_w, out);
}

// round 9
// speedup vs baseline: 1.0150x; 1.0150x over previous
#include <cuda_runtime.h>
#include <cuda_bf16.h>
#include <cstdint>

#define B_    128
#define T_    1024
#define RNN_  1024
#define EMB_  512
#define ATT_  128
#define NF_   32
#define KS_   31
#define PAD_  15

// energies GEMM per 128-t tile: D[128,128] = A[t,192] * B[192,a], B dedup to 128 rows
// s0-3: Ahi x Bhi, s4-7: Alo x Bhi, s8-11: Ahi x Blo
#define LDAB_  136                              // bf16 elems per smem row (272 B)
#define OFF_B_    (128 * LDAB_ * 2)             // 34816
#define OFF_AWR_  (OFF_B_ + 128 * LDAB_ * 2)    // 69632: aw rows 2 x 1056 f
#define OFF_V_    (OFF_AWR_ + 8448)             // 78080
#define OFF_E_    (OFF_V_ + 512)                // 78592: energies 2 x 1024 f
#define OFF_RED_  (OFF_E_ + 8192)               // 86784
#define ESMEM_    (OFF_RED_ + 256)              // 87040

// ---------------- scratch (no allocations allowed) ----------------
__device__ float g_pq[B_ * ATT_];
__device__ __nv_bfloat16 g_W2bf[128 * 128];   // rows 0..63 hi, 64..127 lo (j>=62 zero)

// ---------------- helpers ----------------
__device__ __forceinline__ float tanh_fast(float x) {
    float y; asm("tanh.approx.f32 %0, %1;" : "=f"(y) : "f"(x)); return y;
}
__device__ __forceinline__ uint32_t smem_u32(const void* p) {
    uint32_t a;
    asm("{ .reg .u64 t; cvta.to.shared.u64 t, %1; cvt.u32.u64 %0, t; }" : "=r"(a) : "l"(p));
    return a;
}
__device__ __forceinline__ void ldsm_x4(uint32_t* r, uint32_t addr) {
    asm volatile("ldmatrix.sync.aligned.m8n8.x4.shared.b16 {%0,%1,%2,%3}, [%4];"
                 : "=r"(r[0]), "=r"(r[1]), "=r"(r[2]), "=r"(r[3]) : "r"(addr));
}
__device__ __forceinline__ void ldsm_x2t(uint32_t& b0, uint32_t& b1, uint32_t addr) {
    asm volatile("ldmatrix.sync.aligned.m8n8.x2.trans.shared.b16 {%0,%1}, [%2];"
                 : "=r"(b0), "=r"(b1) : "r"(addr));
}
__device__ __forceinline__ void mma_bf16(float* d, const uint32_t* a, uint32_t b0, uint32_t b1) {
    asm volatile("mma.sync.aligned.m16n8k16.row.col.f32.bf16.bf16.f32 "
                 "{%0,%1,%2,%3}, {%4,%5,%6,%7}, {%8,%9}, {%0,%1,%2,%3};"
                 : "+f"(d[0]), "+f"(d[1]), "+f"(d[2]), "+f"(d[3])
                 : "r"(a[0]), "r"(a[1]), "r"(a[2]), "r"(a[3]), "r"(b0), "r"(b1));
}

// ================= K1: prep =================
// blocks 0..127: pq row b. 256 threads = 32 a-quads x 8 k-eighths, float4 loads.
// block 128: W2 build.
__global__ __launch_bounds__(256) void prep_kernel(
    const float* __restrict__ hidden, const float* __restrict__ wq,
    const float* __restrict__ wconv,  const float* __restrict__ wloc)
{
    __shared__ float s_buf[8192];
    const int tid = threadIdx.x;

    if (blockIdx.x < 128) {
        const int b = blockIdx.x;
        float*  s_h    = s_buf;                       // 1024 f
        float4* s_part = (float4*)(s_buf + 1024);     // [8][32] float4

        #pragma unroll
        for (int i = 0; i < 4; ++i)
            s_h[tid + 256 * i] = hidden[(size_t)b * RNN_ + tid + 256 * i];
        __syncthreads();

        const int a4 = tid & 31;          // float4 column group
        const int kq = tid >> 5;          // 0..7, 128 k each
        const float4* wq4 = (const float4*)wq + (size_t)(kq * 128) * (ATT_ / 4) + a4;
        const float*  hp  = s_h + kq * 128;

        float4 acc0 = make_float4(0.f, 0.f, 0.f, 0.f);
        float4 acc1 = make_float4(0.f, 0.f, 0.f, 0.f);
        #pragma unroll 8
        for (int k = 0; k < 128; k += 2) {
            float h0 = hp[k], h1 = hp[k + 1];
            float4 w0 = wq4[(size_t)k * (ATT_ / 4)];
            float4 w1 = wq4[(size_t)(k + 1) * (ATT_ / 4)];
            acc0.x = fmaf(h0, w0.x, acc0.x);
            acc0.y = fmaf(h0, w0.y, acc0.y);
            acc0.z = fmaf(h0, w0.z, acc0.z);
            acc0.w = fmaf(h0, w0.w, acc0.w);
            acc1.x = fmaf(h1, w1.x, acc1.x);
            acc1.y = fmaf(h1, w1.y, acc1.y);
            acc1.z = fmaf(h1, w1.z, acc1.z);
            acc1.w = fmaf(h1, w1.w, acc1.w);
        }
        acc0.x += acc1.x; acc0.y += acc1.y; acc0.z += acc1.z; acc0.w += acc1.w;
        s_part[kq * 32 + a4] = acc0;
        __syncthreads();

        if (tid < 32) {
            float4 r = s_part[tid];
            #pragma unroll
            for (int q = 1; q < 8; ++q) {
                float4 v = s_part[q * 32 + tid];
                r.x += v.x; r.y += v.y; r.z += v.z; r.w += v.w;
            }
            ((float4*)g_pq)[b * (ATT_ / 4) + tid] = r;
        }
    } else {
        // W2[j,a] = sum_f wconv[f*62+j] * wloc[f*128+a], j in [0,62)
        float* s_W2 = s_buf;
        for (int m = tid; m < 62 * 128; m += 256) {
            int j = m >> 7, a = m & 127;
            float acc = 0.f;
            #pragma unroll 8
            for (int f = 0; f < NF_; ++f)
                acc = fmaf(wconv[f * 62 + j], wloc[f * ATT_ + a], acc);
            s_W2[m] = acc;
        }
        __syncthreads();
        for (int m = tid; m < 128 * 128; m += 256) {
            int row = m >> 7, a = m & 127;
            int seg = row >> 6, j = row & 63;
            __nv_bfloat16 out = __float2bfloat16_rn(0.f);
            if (j < 62) {
                float w = s_W2[j * 128 + a];
                __nv_bfloat16 hi = __float2bfloat16_rn(w);
                out = (seg == 0) ? hi : __float2bfloat16_rn(w - __bfloat162float(hi));
            }
            g_W2bf[m] = out;
        }
    }
}

// ============ K2: energies (MMA over 8 t-tiles, 16 warps) + fused softmax, 1 block/b ============
__global__ __launch_bounds__(512, 1) void energies_softmax_kernel(
    const float* __restrict__ aw,      // [B,2,T]
    const float* __restrict__ pmem,    // [B,T,ATT]
    const float* __restrict__ vvec,    // [ATT]
    const unsigned char* __restrict__ mask,
    float* __restrict__ out_w)
{
    extern __shared__ __align__(16) char sm[];
    const uint32_t sbase = smem_u32(sm);

    const int b    = blockIdx.x;
    const int tid  = threadIdx.x;
    const int wm   = tid >> 5, lane = tid & 31;
    const int slab = wm >> 1;          // 0..7: t rows [16*slab, 16*slab+16)
    const int nh   = wm & 1;           // 0..1: n-tiles [8*nh, 8*nh+8)

    float* s_awr = (float*)(sm + OFF_AWR_);   // [2][1056], s_awr[ch][i] = aw[gt=i-16]
    float* s_v   = (float*)(sm + OFF_V_);
    float* s_e   = (float*)(sm + OFF_E_);     // [2][1024] per-nh partials
    float* s_red = (float*)(sm + OFF_RED_);

    // ---- one-time staging ----
    {
        const uint32_t* gw = (const uint32_t*)g_W2bf;   // [128][64] u32
        for (int m = tid; m < 128 * 64; m += 512) {
            int r = m >> 6, c = m & 63;
            *(uint32_t*)(sm + OFF_B_ + r * (LDAB_ * 2) + c * 4) = gw[m];
        }
    }
    for (int idx = tid; idx < 2112; idx += 512) {
        int ch = idx / 1056, i = idx - ch * 1056;
        int gt = i - 16;
        s_awr[idx] = (gt >= 0 && gt < T_) ? aw[((size_t)b * 2 + ch) * T_ + gt] : 0.f;
    }
    if (tid < 128) {
        s_v[tid] = vvec[tid];
        float q = g_pq[b * ATT_ + tid];
        __nv_bfloat16 hi = __float2bfloat16_rn(q);
        __nv_bfloat16 lo = __float2bfloat16_rn(q - __bfloat162float(hi));
        __nv_bfloat16* sB = (__nv_bfloat16*)(sm + OFF_B_);
        sB[ 62 * LDAB_ + tid] = hi;
        sB[126 * LDAB_ + tid] = lo;
        __nv_bfloat16* arow = (__nv_bfloat16*)(sm + tid * (LDAB_ * 2));
        arow[62]  = __float2bfloat16_rn(1.f);
        arow[63]  = __float2bfloat16_rn(0.f);
        arow[126] = __float2bfloat16_rn(0.f);
        arow[127] = __float2bfloat16_rn(0.f);
    }

    const uint32_t aRowAddr = sbase + (16 * slab + (lane & 15)) * (LDAB_ * 2) + (lane >> 4) * 16;
    const uint32_t bRowAddr = sbase + OFF_B_ + (lane & 15) * (LDAB_ * 2) + nh * 128;
    const int rowL = tid >> 2;            // A row this thread builds
    const int jq   = tid & 3;             // 16-col group within the row

    // ---- 8 t-tiles ----
    for (int it = 0; it < 8; ++it) {
        const int t0g = it * 128;

        __syncthreads();
        {
            __nv_bfloat16* arow = (__nv_bfloat16*)(sm + rowL * (LDAB_ * 2));
            const int base0 = 1 + t0g + rowL;
            #pragma unroll
            for (int q = 0; q < 16; ++q) {
                int j = jq * 16 + q;
                if (j < 62) {
                    float x = (j < 31) ? s_awr[base0 + j] : s_awr[1056 + base0 + (j - 31)];
                    __nv_bfloat16 hi = __float2bfloat16_rn(x);
                    arow[j]      = hi;
                    arow[64 + j] = __float2bfloat16_rn(x - __bfloat162float(hi));
                }
            }
        }
        __syncthreads();

        float acc[8][4];
        #pragma unroll
        for (int n = 0; n < 8; ++n) {
            acc[n][0] = 0.f; acc[n][1] = 0.f; acc[n][2] = 0.f; acc[n][3] = 0.f;
        }
        #pragma unroll
        for (int s = 0; s < 12; ++s) {
            const int ksa = (s < 8) ? s : (s - 8);
            const int ksb = (s < 4) ? s : (s - 4);
            uint32_t af[4];
            ldsm_x4(af, aRowAddr + ksa * 32);
            const uint32_t bS = bRowAddr + ksb * 16 * (LDAB_ * 2);
            #pragma unroll
            for (int n = 0; n < 8; ++n) {
                uint32_t b0, b1;
                ldsm_x2t(b0, b1, bS + n * 16);
                mma_bf16(acc[n], af, b0, b1);
            }
        }

        {
            const int r  = lane >> 2;
            const int cq = (lane & 3) * 2;
            const int tA = t0g + 16 * slab + r;
            const float* pmA = pmem + ((size_t)b * T_ + tA) * ATT_;
            const float* pmB = pmA + 8 * ATT_;
            float eA = 0.f, eB = 0.f;
            #pragma unroll
            for (int n = 0; n < 8; ++n) {
                const int col = 64 * nh + 8 * n + cq;
                float2 v2 = *(const float2*)(s_v + col);
                float2 pa = *(const float2*)(pmA + col);
                float2 pb = *(const float2*)(pmB + col);
                eA = fmaf(tanh_fast(acc[n][0] + pa.x), v2.x, eA);
                eA = fmaf(tanh_fast(acc[n][1] + pa.y), v2.y, eA);
                eB = fmaf(tanh_fast(acc[n][2] + pb.x), v2.x, eB);
                eB = fmaf(tanh_fast(acc[n][3] + pb.y), v2.y, eB);
            }
            eA += __shfl_xor_sync(0xffffffffu, eA, 1);
            eA += __shfl_xor_sync(0xffffffffu, eA, 2);
            eB += __shfl_xor_sync(0xffffffffu, eB, 1);
            eB += __shfl_xor_sync(0xffffffffu, eB, 2);
            if ((lane & 3) == 0) {
                s_e[nh * 1024 + tA]     = eA;
                s_e[nh * 1024 + tA + 8] = eB;
            }
        }
    }
    __syncthreads();

    // ---- fused softmax over 1024 energies ----
    {
        float2 e0 = ((const float2*)s_e)[tid];
        float2 e1 = ((const float2*)(s_e + 1024))[tid];
        float2 ev; ev.x = e0.x + e1.x; ev.y = e0.y + e1.y;
        const uchar2 mk = ((const uchar2*)(mask + (size_t)b * T_))[tid];
        const float NINF = -__int_as_float(0x7f800000);
        if (mk.x) ev.x = NINF;
        if (mk.y) ev.y = NINF;

        float m = fmaxf(ev.x, ev.y);
        #pragma unroll
        for (int o = 16; o; o >>= 1) m = fmaxf(m, __shfl_xor_sync(0xffffffffu, m, o));
        if (lane == 0) s_red[wm] = m;
        __syncthreads();
        if (wm == 0) {
            float mm = (lane < 16) ? s_red[lane] : NINF;
            #pragma unroll
            for (int o = 8; o; o >>= 1) mm = fmaxf(mm, __shfl_xor_sync(0xffffffffu, mm, o));
            if (lane == 0) s_red[16] = mm;
        }
        __syncthreads();
        m = s_red[16];

        float2 p;
        p.x = expf(ev.x - m); p.y = expf(ev.y - m);
        float s = p.x + p.y;
        #pragma unroll
        for (int o = 16; o; o >>= 1) s += __shfl_xor_sync(0xffffffffu, s, o);
        if (lane == 0) s_red[32 + wm] = s;
        __syncthreads();
        if (wm == 0) {
            float ss = (lane < 16) ? s_red[32 + lane] : 0.f;
            #pragma unroll
            for (int o = 8; o; o >>= 1) ss += __shfl_xor_sync(0xffffffffu, ss, o);
            if (lane == 0) s_red[48] = ss;
        }
        __syncthreads();
        const float inv = 1.f / s_red[48];

        p.x *= inv; p.y *= inv;
        ((float2*)(out_w + (size_t)b * T_))[tid] = p;
    }
}

// ============ K3: context, single pass: grid (4, B_), 256 thr ============
__global__ __launch_bounds__(256) void context_kernel(
    const float* __restrict__ memory,   // [B,T,EMB]
    const float* __restrict__ out_w,    // weights [B,T]
    float* __restrict__ out)            // context [B,EMB]
{
    const int ec = blockIdx.x, b = blockIdx.y;
    const int tid = threadIdx.x;
    const int g = tid >> 5, l = tid & 31;

    __shared__ float s_w[T_];
    __shared__ float4 s_acc[256];

    #pragma unroll
    for (int i = 0; i < 4; ++i)
        s_w[tid + 256 * i] = out_w[(size_t)b * T_ + tid + 256 * i];
    __syncthreads();

    const float4* mem4 = (const float4*)memory + ((size_t)b * T_) * (EMB_ / 4) + ec * 32 + l;
    float4 acc = make_float4(0.f, 0.f, 0.f, 0.f);
    #pragma unroll 4
    for (int t = g; t < T_; t += 8) {
        float wt = s_w[t];
        float4 mv = __ldcs(mem4 + (size_t)t * (EMB_ / 4));
        acc.x = fmaf(wt, mv.x, acc.x);
        acc.y = fmaf(wt, mv.y, acc.y);
        acc.z = fmaf(wt, mv.z, acc.z);
        acc.w = fmaf(wt, mv.w, acc.w);
    }
    s_acc[tid] = acc;
    __syncthreads();
    if (g < 4) {
        float4 o = s_acc[tid + 128];
        acc.x += o.x; acc.y += o.y; acc.z += o.z; acc.w += o.w;
        s_acc[tid] = acc;
    }
    __syncthreads();
    if (g < 2) {
        float4 o = s_acc[tid + 64];
        acc.x += o.x; acc.y += o.y; acc.z += o.z; acc.w += o.w;
        s_acc[tid] = acc;
    }
    __syncthreads();
    if (g == 0) {
        float4 o = s_acc[tid + 32];
        acc.x += o.x; acc.y += o.y; acc.z += o.z; acc.w += o.w;
        ((float4*)out)[(size_t)b * (EMB_ / 4) + ec * 32 + l] = acc;
    }
}

// ============================ launch ============================
extern "C" void kernel_launch(void* const* d_in, const int* in_sizes, int n_in,
                              void* d_out, int out_size) {
    const float* hidden = (const float*)d_in[0];
    const float* memory = (const float*)d_in[1];
    const float* pmem   = (const float*)d_in[2];
    const float* awcat  = (const float*)d_in[3];
    const unsigned char* mask = (const unsigned char*)d_in[4];
    const float* wq     = (const float*)d_in[5];
    const float* wconv  = (const float*)d_in[6];
    const float* wloc   = (const float*)d_in[7];
    const float* vvec   = (const float*)d_in[8];

    float* out   = (float*)d_out;
    float* out_w = out + (size_t)B_ * EMB_;

    cudaFuncSetAttribute(energies_softmax_kernel,
                         cudaFuncAttributeMaxDynamicSharedMemorySize, ESMEM_);

    prep_kernel<<<129, 256>>>(hidden, wq, wconv, wloc);
    energies_softmax_kernel<<<B_, 512, ESMEM_>>>(awcat, pmem, vvec, mask, out_w);
    context_kernel<<<dim3(4, B_), 256>>>(memory, out_w, out);
}

// round 10
// speedup vs baseline: 1.2420x; 1.2237x over previous
#include <cuda_runtime.h>
#include <cuda_bf16.h>
#include <cstdint>

#define B_    128
#define T_    1024
#define RNN_  1024
#define EMB_  512
#define ATT_  128
#define NF_   32
#define KS_   31
#define PAD_  15

// energies GEMM per 128-t tile: D[128,128] = A[t,192] * B[192,a], B dedup to 128 rows
// s0-3: Ahi x Bhi, s4-7: Alo x Bhi, s8-11: Ahi x Blo
#define LDAB_  136                              // bf16 elems per smem row (272 B)
#define OFF_B_    (128 * LDAB_ * 2)             // 34816
#define OFF_AWR_  (OFF_B_ + 128 * LDAB_ * 2)    // 69632: aw rows 2 x 1056 f
#define OFF_V_    (OFF_AWR_ + 8448)             // 78080
#define OFF_E_    (OFF_V_ + 512)                // 78592: energies 2 x 1024 f (also pq scratch)
#define OFF_RED_  (OFF_E_ + 8192)               // 86784
#define OFF_HID_  (OFF_RED_ + 256)              // 87040: hidden row 1024 f
#define ESMEM_    (OFF_HID_ + 4096)             // 91136

// scratch inside the (not yet built) A region during staging:
#define SCR_WLOC_  0          // 4096 f = 16384 B
#define SCR_WCONV_ 16384      // 1984 f = 7936 B (ends at 24320 < 34816)

// ---------------- helpers ----------------
__device__ __forceinline__ float tanh_fast(float x) {
    float y; asm("tanh.approx.f32 %0, %1;" : "=f"(y) : "f"(x)); return y;
}
__device__ __forceinline__ uint32_t smem_u32(const void* p) {
    uint32_t a;
    asm("{ .reg .u64 t; cvta.to.shared.u64 t, %1; cvt.u32.u64 %0, t; }" : "=r"(a) : "l"(p));
    return a;
}
__device__ __forceinline__ void ldsm_x4(uint32_t* r, uint32_t addr) {
    asm volatile("ldmatrix.sync.aligned.m8n8.x4.shared.b16 {%0,%1,%2,%3}, [%4];"
                 : "=r"(r[0]), "=r"(r[1]), "=r"(r[2]), "=r"(r[3]) : "r"(addr));
}
__device__ __forceinline__ void ldsm_x2t(uint32_t& b0, uint32_t& b1, uint32_t addr) {
    asm volatile("ldmatrix.sync.aligned.m8n8.x2.trans.shared.b16 {%0,%1}, [%2];"
                 : "=r"(b0), "=r"(b1) : "r"(addr));
}
__device__ __forceinline__ void mma_bf16(float* d, const uint32_t* a, uint32_t b0, uint32_t b1) {
    asm volatile("mma.sync.aligned.m16n8k16.row.col.f32.bf16.bf16.f32 "
                 "{%0,%1,%2,%3}, {%4,%5,%6,%7}, {%8,%9}, {%0,%1,%2,%3};"
                 : "+f"(d[0]), "+f"(d[1]), "+f"(d[2]), "+f"(d[3])
                 : "r"(a[0]), "r"(a[1]), "r"(a[2]), "r"(a[3]), "r"(b0), "r"(b1));
}

// ====== K1: fully-fused energies: pq + W2 + MMA(8 t-tiles) + softmax, 1 block/b ======
__global__ __launch_bounds__(512, 1) void energies_softmax_kernel(
    const float* __restrict__ aw,      // [B,2,T]
    const float* __restrict__ pmem,    // [B,T,ATT]
    const float* __restrict__ vvec,    // [ATT]
    const unsigned char* __restrict__ mask,
    const float* __restrict__ hidden,  // [B,RNN]
    const float* __restrict__ wq,      // [RNN,ATT]
    const float* __restrict__ wconv,   // [NF,2,KS] = [NF,62]
    const float* __restrict__ wloc,    // [NF,ATT]
    float* __restrict__ out_w)
{
    extern __shared__ __align__(16) char sm[];
    const uint32_t sbase = smem_u32(sm);

    const int b    = blockIdx.x;
    const int tid  = threadIdx.x;
    const int wm   = tid >> 5, lane = tid & 31;
    const int slab = wm >> 1;          // 0..7: t rows [16*slab, 16*slab+16)
    const int nh   = wm & 1;           // 0..1: n-tiles [8*nh, 8*nh+8)

    float* s_awr = (float*)(sm + OFF_AWR_);   // [2][1056], s_awr[ch][i] = aw[gt=i-16]
    float* s_v   = (float*)(sm + OFF_V_);
    float* s_e   = (float*)(sm + OFF_E_);     // [2][1024]; pq-partial scratch early
    float* s_red = (float*)(sm + OFF_RED_);
    float* s_hid = (float*)(sm + OFF_HID_);
    __nv_bfloat16* sB = (__nv_bfloat16*)(sm + OFF_B_);

    // ---------- staging: aw window, v, hidden, wconv/wloc scratch ----------
    for (int idx = tid; idx < 2112; idx += 512) {
        int ch = idx / 1056, i = idx - ch * 1056;
        int gt = i - 16;
        s_awr[idx] = (gt >= 0 && gt < T_) ? aw[((size_t)b * 2 + ch) * T_ + gt] : 0.f;
    }
    if (tid < 128) s_v[tid] = vvec[tid];
    s_hid[tid]       = hidden[(size_t)b * RNN_ + tid];
    s_hid[tid + 512] = hidden[(size_t)b * RNN_ + tid + 512];
    {
        float* s_wloc  = (float*)(sm + SCR_WLOC_);
        float* s_wconv = (float*)(sm + SCR_WCONV_);
        #pragma unroll
        for (int i = 0; i < 8; ++i) s_wloc[tid + 512 * i] = wloc[tid + 512 * i];
        for (int m = tid; m < NF_ * 62; m += 512) s_wconv[m] = wconv[m];
    }
    __syncthreads();

    // ---------- phase A: pq partials + W2 -> B rows ----------
    {
        // pq partials: 32 a-quads x 16 k-strips of 64
        const int kq = tid >> 5, a4 = tid & 31;
        const float4* wq4 = (const float4*)wq + (size_t)(kq * 64) * (ATT_ / 4) + a4;
        const float*  hp  = s_hid + kq * 64;
        float4 acc0 = make_float4(0.f, 0.f, 0.f, 0.f);
        float4 acc1 = make_float4(0.f, 0.f, 0.f, 0.f);
        #pragma unroll 8
        for (int k = 0; k < 64; k += 2) {
            float h0 = hp[k], h1 = hp[k + 1];
            float4 w0 = wq4[(size_t)k * (ATT_ / 4)];
            float4 w1 = wq4[(size_t)(k + 1) * (ATT_ / 4)];
            acc0.x = fmaf(h0, w0.x, acc0.x);
            acc0.y = fmaf(h0, w0.y, acc0.y);
            acc0.z = fmaf(h0, w0.z, acc0.z);
            acc0.w = fmaf(h0, w0.w, acc0.w);
            acc1.x = fmaf(h1, w1.x, acc1.x);
            acc1.y = fmaf(h1, w1.y, acc1.y);
            acc1.z = fmaf(h1, w1.z, acc1.z);
            acc1.w = fmaf(h1, w1.w, acc1.w);
        }
        acc0.x += acc1.x; acc0.y += acc1.y; acc0.z += acc1.z; acc0.w += acc1.w;
        ((float4*)s_e)[kq * 32 + a4] = acc0;

        // W2[j,a] -> B rows j (hi) and 64+j (lo)
        const float* s_wloc  = (const float*)(sm + SCR_WLOC_);
        const float* s_wconv = (const float*)(sm + SCR_WCONV_);
        for (int m = tid; m < 62 * 128; m += 512) {
            int j = m >> 7, a = m & 127;
            float acc = 0.f;
            #pragma unroll 8
            for (int f = 0; f < NF_; ++f)
                acc = fmaf(s_wconv[f * 62 + j], s_wloc[f * ATT_ + a], acc);
            __nv_bfloat16 hi = __float2bfloat16_rn(acc);
            sB[j * LDAB_ + a]        = hi;
            sB[(64 + j) * LDAB_ + a] = __float2bfloat16_rn(acc - __bfloat162float(hi));
        }
        if (tid < 128) {   // rows 63/127: A col is 0 there, but avoid NaN garbage
            sB[ 63 * LDAB_ + tid] = __float2bfloat16_rn(0.f);
            sB[127 * LDAB_ + tid] = __float2bfloat16_rn(0.f);
        }
    }
    __syncthreads();

    // ---------- phase B: pq reduce -> B rows 62/126; const A cols ----------
    if (tid < 32) {
        float4 r = ((const float4*)s_e)[tid];
        #pragma unroll
        for (int q = 1; q < 16; ++q) {
            float4 v = ((const float4*)s_e)[q * 32 + tid];
            r.x += v.x; r.y += v.y; r.z += v.z; r.w += v.w;
        }
        float vals[4] = {r.x, r.y, r.z, r.w};
        #pragma unroll
        for (int c = 0; c < 4; ++c) {
            int col = 4 * tid + c;
            __nv_bfloat16 hi = __float2bfloat16_rn(vals[c]);
            sB[ 62 * LDAB_ + col] = hi;
            sB[126 * LDAB_ + col] = __float2bfloat16_rn(vals[c] - __bfloat162float(hi));
        }
    }
    if (tid < 128) {       // scratch is dead now; set constant A columns
        __nv_bfloat16* arow = (__nv_bfloat16*)(sm + tid * (LDAB_ * 2));
        arow[62]  = __float2bfloat16_rn(1.f);
        arow[63]  = __float2bfloat16_rn(0.f);
        arow[126] = __float2bfloat16_rn(0.f);
        arow[127] = __float2bfloat16_rn(0.f);
    }

    const uint32_t aRowAddr = sbase + (16 * slab + (lane & 15)) * (LDAB_ * 2) + (lane >> 4) * 16;
    const uint32_t bRowAddr = sbase + OFF_B_ + (lane & 15) * (LDAB_ * 2) + nh * 128;
    const int rowL = tid >> 2;            // A row this thread builds
    const int jq   = tid & 3;             // 16-col group within the row

    // ---------- 8 t-tiles ----------
    for (int it = 0; it < 8; ++it) {
        const int t0g = it * 128;

        __syncthreads();
        {
            __nv_bfloat16* arow = (__nv_bfloat16*)(sm + rowL * (LDAB_ * 2));
            const int base0 = 1 + t0g + rowL;
            #pragma unroll
            for (int q = 0; q < 16; ++q) {
                int j = jq * 16 + q;
                if (j < 62) {
                    float x = (j < 31) ? s_awr[base0 + j] : s_awr[1056 + base0 + (j - 31)];
                    __nv_bfloat16 hi = __float2bfloat16_rn(x);
                    arow[j]      = hi;
                    arow[64 + j] = __float2bfloat16_rn(x - __bfloat162float(hi));
                }
            }
        }
        __syncthreads();

        float acc[8][4];
        #pragma unroll
        for (int n = 0; n < 8; ++n) {
            acc[n][0] = 0.f; acc[n][1] = 0.f; acc[n][2] = 0.f; acc[n][3] = 0.f;
        }
        #pragma unroll
        for (int s = 0; s < 12; ++s) {
            const int ksa = (s < 8) ? s : (s - 8);
            const int ksb = (s < 4) ? s : (s - 4);
            uint32_t af[4];
            ldsm_x4(af, aRowAddr + ksa * 32);
            const uint32_t bS = bRowAddr + ksb * 16 * (LDAB_ * 2);
            #pragma unroll
            for (int n = 0; n < 8; ++n) {
                uint32_t b0, b1;
                ldsm_x2t(b0, b1, bS + n * 16);
                mma_bf16(acc[n], af, b0, b1);
            }
        }

        {
            const int r  = lane >> 2;
            const int cq = (lane & 3) * 2;
            const int tA = t0g + 16 * slab + r;
            const float* pmA = pmem + ((size_t)b * T_ + tA) * ATT_;
            const float* pmB = pmA + 8 * ATT_;
            float eA = 0.f, eB = 0.f;
            #pragma unroll
            for (int n = 0; n < 8; ++n) {
                const int col = 64 * nh + 8 * n + cq;
                float2 v2 = *(const float2*)(s_v + col);
                float2 pa = *(const float2*)(pmA + col);
                float2 pb = *(const float2*)(pmB + col);
                eA = fmaf(tanh_fast(acc[n][0] + pa.x), v2.x, eA);
                eA = fmaf(tanh_fast(acc[n][1] + pa.y), v2.y, eA);
                eB = fmaf(tanh_fast(acc[n][2] + pb.x), v2.x, eB);
                eB = fmaf(tanh_fast(acc[n][3] + pb.y), v2.y, eB);
            }
            eA += __shfl_xor_sync(0xffffffffu, eA, 1);
            eA += __shfl_xor_sync(0xffffffffu, eA, 2);
            eB += __shfl_xor_sync(0xffffffffu, eB, 1);
            eB += __shfl_xor_sync(0xffffffffu, eB, 2);
            if ((lane & 3) == 0) {
                s_e[nh * 1024 + tA]     = eA;
                s_e[nh * 1024 + tA + 8] = eB;
            }
        }
    }
    __syncthreads();

    // ---------- fused softmax over 1024 energies ----------
    {
        float2 e0 = ((const float2*)s_e)[tid];
        float2 e1 = ((const float2*)(s_e + 1024))[tid];
        float2 ev; ev.x = e0.x + e1.x; ev.y = e0.y + e1.y;
        const uchar2 mk = ((const uchar2*)(mask + (size_t)b * T_))[tid];
        const float NINF = -__int_as_float(0x7f800000);
        if (mk.x) ev.x = NINF;
        if (mk.y) ev.y = NINF;

        float m = fmaxf(ev.x, ev.y);
        #pragma unroll
        for (int o = 16; o; o >>= 1) m = fmaxf(m, __shfl_xor_sync(0xffffffffu, m, o));
        if (lane == 0) s_red[wm] = m;
        __syncthreads();
        if (wm == 0) {
            float mm = (lane < 16) ? s_red[lane] : NINF;
            #pragma unroll
            for (int o = 8; o; o >>= 1) mm = fmaxf(mm, __shfl_xor_sync(0xffffffffu, mm, o));
            if (lane == 0) s_red[16] = mm;
        }
        __syncthreads();
        m = s_red[16];

        float2 p;
        p.x = expf(ev.x - m); p.y = expf(ev.y - m);
        float s = p.x + p.y;
        #pragma unroll
        for (int o = 16; o; o >>= 1) s += __shfl_xor_sync(0xffffffffu, s, o);
        if (lane == 0) s_red[32 + wm] = s;
        __syncthreads();
        if (wm == 0) {
            float ss = (lane < 16) ? s_red[32 + lane] : 0.f;
            #pragma unroll
            for (int o = 8; o; o >>= 1) ss += __shfl_xor_sync(0xffffffffu, ss, o);
            if (lane == 0) s_red[48] = ss;
        }
        __syncthreads();
        const float inv = 1.f / s_red[48];

        p.x *= inv; p.y *= inv;
        ((float2*)(out_w + (size_t)b * T_))[tid] = p;
    }
}

// ============ K2: context, single pass: grid (4, B_), 256 thr ============
__global__ __launch_bounds__(256) void context_kernel(
    const float* __restrict__ memory,   // [B,T,EMB]
    const float* __restrict__ out_w,    // weights [B,T]
    float* __restrict__ out)            // context [B,EMB]
{
    const int ec = blockIdx.x, b = blockIdx.y;
    const int tid = threadIdx.x;
    const int g = tid >> 5, l = tid & 31;

    __shared__ float s_w[T_];
    __shared__ float4 s_acc[256];

    #pragma unroll
    for (int i = 0; i < 4; ++i)
        s_w[tid + 256 * i] = out_w[(size_t)b * T_ + tid + 256 * i];
    __syncthreads();

    const float4* mem4 = (const float4*)memory + ((size_t)b * T_) * (EMB_ / 4) + ec * 32 + l;
    float4 acc = make_float4(0.f, 0.f, 0.f, 0.f);
    #pragma unroll 4
    for (int t = g; t < T_; t += 8) {
        float wt = s_w[t];
        float4 mv = __ldcs(mem4 + (size_t)t * (EMB_ / 4));
        acc.x = fmaf(wt, mv.x, acc.x);
        acc.y = fmaf(wt, mv.y, acc.y);
        acc.z = fmaf(wt, mv.z, acc.z);
        acc.w = fmaf(wt, mv.w, acc.w);
    }
    s_acc[tid] = acc;
    __syncthreads();
    if (g < 4) {
        float4 o = s_acc[tid + 128];
        acc.x += o.x; acc.y += o.y; acc.z += o.z; acc.w += o.w;
        s_acc[tid] = acc;
    }
    __syncthreads();
    if (g < 2) {
        float4 o = s_acc[tid + 64];
        acc.x += o.x; acc.y += o.y; acc.z += o.z; acc.w += o.w;
        s_acc[tid] = acc;
    }
    __syncthreads();
    if (g == 0) {
        float4 o = s_acc[tid + 32];
        acc.x += o.x; acc.y += o.y; acc.z += o.z; acc.w += o.w;
        ((float4*)out)[(size_t)b * (EMB_ / 4) + ec * 32 + l] = acc;
    }
}

// ============================ launch ============================
extern "C" void kernel_launch(void* const* d_in, const int* in_sizes, int n_in,
                              void* d_out, int out_size) {
    const float* hidden = (const float*)d_in[0];
    const float* memory = (const float*)d_in[1];
    const float* pmem   = (const float*)d_in[2];
    const float* awcat  = (const float*)d_in[3];
    const unsigned char* mask = (const unsigned char*)d_in[4];
    const float* wq     = (const float*)d_in[5];
    const float* wconv  = (const float*)d_in[6];
    const float* wloc   = (const float*)d_in[7];
    const float* vvec   = (const float*)d_in[8];

    float* out   = (float*)d_out;
    float* out_w = out + (size_t)B_ * EMB_;

    cudaFuncSetAttribute(energies_softmax_kernel,
                         cudaFuncAttributeMaxDynamicSharedMemorySize, ESMEM_);

    energies_softmax_kernel<<<B_, 512, ESMEM_>>>(awcat, pmem, vvec, mask,
                                                 hidden, wq, wconv, wloc, out_w);
    context_kernel<<<dim3(4, B_), 256>>>(memory, out_w, out);
}